// round 5
// baseline (speedup 1.0000x reference)
#include <cuda_runtime.h>
#include <cuda_bf16.h>
#include <cstdint>

// Problem constants
#define NN   10000          // nodes
#define EE   20000          // edges (without self loops)
#define ETOT 30000          // edges + self loops
#define HH   12             // heads
#define CC   768            // per-head dim (== input feature dim)
#define HC   9216           // H*C
#define GGR  64             // graphs

#define MTILES 79           // ceil(10000/128)
#define NTILES 72           // 9216/128
#define FRAG_PER_TILE 98304 // 128*768 floats per (tile, full-K) fragment block

// ---------------- device scratch (static globals; no runtime alloc) --------
__device__ float g_h[(size_t)NN * HC];     // per-layer node features [N, H*C]
__device__ float g_x2[NN * CC];            // layer-1 output / layer-2 input
__device__ float g_y[NN * CC];             // layer-2 output
__device__ float g_Afrag[(size_t)MTILES * FRAG_PER_TILE];  // fragment-major A
__device__ float g_Bfrag[(size_t)NTILES * FRAG_PER_TILE];  // fragment-major W
__device__ float g_Wsd[24 * CC];           // fused score weights [24][768]
__device__ float g_s[NN * HH];             // alpha_src per node/head
__device__ float g_d[NN * HH];             // alpha_dst per node/head
__device__ float g_alpha[ETOT * HH];       // softmax weights, by sorted edge pos
__device__ int   g_indeg[NN];
__device__ int   g_rowptr[NN + 1];
__device__ int   g_fill[NN];
__device__ int   g_ssrc[ETOT];             // source node per CSR position
__device__ float g_pool[GGR * CC];
__device__ int   g_cnt[GGR];
__device__ int   g_gstart[GGR];

// ---------------- helpers ----------------------------------------------------
__device__ __forceinline__ uint32_t smem_u32(const void* p) {
    uint32_t a;
    asm("{ .reg .u64 t; cvta.to.shared.u64 t, %1; cvt.u32.u64 %0, t; }"
        : "=r"(a) : "l"(p));
    return a;
}

__device__ __forceinline__ unsigned f2tf(float f) {
    unsigned u;
    asm("cvt.rna.tf32.f32 %0, %1;" : "=r"(u) : "f"(f));
    return u;
}

__device__ __forceinline__ void mma_tf32(float* d, const unsigned* a,
                                         unsigned b0, unsigned b1) {
    asm volatile(
        "mma.sync.aligned.m16n8k8.row.col.f32.tf32.tf32.f32 "
        "{%0,%1,%2,%3}, {%4,%5,%6,%7}, {%8,%9}, {%0,%1,%2,%3};\n"
        : "+f"(d[0]), "+f"(d[1]), "+f"(d[2]), "+f"(d[3])
        : "r"(a[0]), "r"(a[1]), "r"(a[2]), "r"(a[3]), "r"(b0), "r"(b1));
}

#define CP_ASYNC16(dst, src) \
    asm volatile("cp.async.cg.shared.global [%0], [%1], 16;" :: \
                 "r"(dst), "l"(src) : "memory")
#define CP_COMMIT() asm volatile("cp.async.commit_group;" ::: "memory")
#define CP_WAIT1()  asm volatile("cp.async.wait_group 1;" ::: "memory")
#define CP_WAIT0()  asm volatile("cp.async.wait_group 0;" ::: "memory")

#define LDS128(r0, r1, r2, r3, addr) \
    asm volatile("ld.shared.v4.b32 {%0,%1,%2,%3}, [%4];" \
                 : "=r"(r0), "=r"(r1), "=r"(r2), "=r"(r3) : "r"(addr))

// ---------------- CSR build ------------------------------------------------
__global__ void zero_build_kernel() {
    int i = blockIdx.x * blockDim.x + threadIdx.x;
    if (i < NN) { g_indeg[i] = 0; g_fill[i] = 0; }
    if (i < GGR) { g_cnt[i] = 0; g_gstart[i] = NN; }
}

__global__ void count_deg_kernel(const int* __restrict__ edge_index) {
    int e = blockIdx.x * blockDim.x + threadIdx.x;
    if (e >= ETOT) return;
    int dst = (e < EE) ? edge_index[EE + e] : (e - EE);
    atomicAdd(&g_indeg[dst], 1);
}

__global__ void scan_kernel() {
    __shared__ int sd[1024];
    __shared__ int soff;
    int t = threadIdx.x;
    if (t == 0) { soff = 0; g_rowptr[0] = 0; }
    __syncthreads();
    for (int base = 0; base < NN; base += 1024) {
        int i = base + t;
        int v = (i < NN) ? g_indeg[i] : 0;
        sd[t] = v;
        __syncthreads();
        for (int off = 1; off < 1024; off <<= 1) {
            int tmp = (t >= off) ? sd[t - off] : 0;
            __syncthreads();
            sd[t] += tmp;
            __syncthreads();
        }
        if (i < NN) g_rowptr[i + 1] = soff + sd[t];
        __syncthreads();
        if (t == 0) soff += sd[1023];
        __syncthreads();
    }
}

__global__ void fill_csr_kernel(const int* __restrict__ edge_index) {
    int e = blockIdx.x * blockDim.x + threadIdx.x;
    if (e >= ETOT) return;
    int src = (e < EE) ? edge_index[e]      : (e - EE);
    int dst = (e < EE) ? edge_index[EE + e] : (e - EE);
    int pos = g_rowptr[dst] + atomicAdd(&g_fill[dst], 1);
    g_ssrc[pos] = src;
}

// graph start offsets (batch sorted -> contiguous segments)
__global__ void graph_start_kernel(const int* __restrict__ batch) {
    int n = blockIdx.x * blockDim.x + threadIdx.x;
    if (n < NN) {
        atomicMin(&g_gstart[batch[n]], n);
        atomicAdd(&g_cnt[batch[n]], 1);
    }
}

// ---------------- operand packing into fragment-major layout -----------------
__global__ __launch_bounds__(256)
void prep_A_kernel(const float* __restrict__ src, int M) {
    __shared__ float st[128 * 68];       // 128 rows x 64 cols, pitch 68
    int tid = threadIdx.x, lane = tid & 31, wid = tid >> 5;
    int mtile = blockIdx.x, kgrp = blockIdx.y;   // kgrp covers 64 k
#pragma unroll
    for (int i = 0; i < 8; i++) {
        int idx = tid + i * 256;         // 0..2047
        int row = idx >> 4, c4 = idx & 15;
        int m = mtile * 128 + row;
        float4 v = make_float4(0.f, 0.f, 0.f, 0.f);
        if (m < M) v = *(const float4*)&src[(size_t)m * CC + kgrp * 64 + c4 * 4];
        *(float4*)&st[row * 68 + c4 * 4] = v;
    }
    __syncthreads();
    int g = lane >> 2, tg = lane & 3;
#pragma unroll
    for (int t = 0; t < 8; t++) {
        int fb = wid * 8 + t;
        int kbl = fb & 7, m16 = fb >> 3;
        uint4 o;
        o.x = f2tf(st[(m16 * 16 + g    ) * 68 + kbl * 8 + tg    ]);
        o.y = f2tf(st[(m16 * 16 + g + 8) * 68 + kbl * 8 + tg    ]);
        o.z = f2tf(st[(m16 * 16 + g    ) * 68 + kbl * 8 + tg + 4]);
        o.w = f2tf(st[(m16 * 16 + g + 8) * 68 + kbl * 8 + tg + 4]);
        size_t out = ((size_t)((mtile * 96 + kgrp * 8 + kbl) * 8 + m16)) * 32 + lane;
        ((uint4*)g_Afrag)[out] = o;
    }
}

__global__ __launch_bounds__(256)
void prep_B_kernel(const float* __restrict__ W) {
    __shared__ float st[64 * 132];       // 64 k-rows x 128 n-cols, pitch 132
    int tid = threadIdx.x, lane = tid & 31, wid = tid >> 5;
    int ntile = blockIdx.x, kgrp = blockIdx.y;
#pragma unroll
    for (int i = 0; i < 8; i++) {
        int idx = tid + i * 256;         // 0..2047
        int row = idx >> 5, c4 = idx & 31;
        float4 v = *(const float4*)&W[(size_t)(kgrp * 64 + row) * HC +
                                      ntile * 128 + c4 * 4];
        *(float4*)&st[row * 132 + c4 * 4] = v;
    }
    __syncthreads();
    int g = lane >> 2, tg = lane & 3;
#pragma unroll
    for (int t = 0; t < 8; t++) {
        int fb = wid * 8 + t;
        int kbl = fb & 7, n16 = fb >> 3;
        uint4 o;
        o.x = f2tf(st[(kbl * 8 + tg    ) * 132 + n16 * 16 + g    ]);
        o.y = f2tf(st[(kbl * 8 + tg + 4) * 132 + n16 * 16 + g    ]);
        o.z = f2tf(st[(kbl * 8 + tg    ) * 132 + n16 * 16 + g + 8]);
        o.w = f2tf(st[(kbl * 8 + tg + 4) * 132 + n16 * 16 + g + 8]);
        size_t out = ((size_t)((ntile * 96 + kgrp * 8 + kbl) * 8 + n16)) * 32 + lane;
        ((uint4*)g_Bfrag)[out] = o;
    }
}

// ---------------- fragment-major tf32 mma.sync GEMM --------------------------
#define NCHK 24
#define STAGE_BYTES 32768    // 16KB A + 16KB B

__global__ __launch_bounds__(256)
void frag_gemm_kernel(float* __restrict__ Cm, int M) {
    extern __shared__ char smem[];
    const uint32_t sbase = smem_u32(smem);
    const int tid = threadIdx.x, wid = tid >> 5, lane = tid & 31;
    const int mtile = blockIdx.y, ntile = blockIdx.x;
    const char* Abase = (const char*)g_Afrag + (size_t)mtile * FRAG_PER_TILE * 4;
    const char* Bbase = (const char*)g_Bfrag + (size_t)ntile * FRAG_PER_TILE * 4;

    const int g = lane >> 2, tg = lane & 3;
    const int mb16 = (wid & 3) * 2;      // m16 base for this warp (2 blocks)
    const int nb16 = (wid >> 2) * 4;     // n16 base (4 blocks)

    float acc[2][8][4];
#pragma unroll
    for (int i = 0; i < 2; i++)
#pragma unroll
        for (int j = 0; j < 8; j++)
#pragma unroll
            for (int q = 0; q < 4; q++) acc[i][j][q] = 0.f;

#define STAGE_CP(buf, chunk)                                              \
    {                                                                     \
        const char* as = Abase + (size_t)(chunk) * 16384 + tid * 16;      \
        const char* bs = Bbase + (size_t)(chunk) * 16384 + tid * 16;      \
        uint32_t ad = sbase + (buf) * STAGE_BYTES + tid * 16;             \
        uint32_t bd = ad + 16384;                                         \
        _Pragma("unroll")                                                 \
        for (int i = 0; i < 4; i++) {                                     \
            CP_ASYNC16(ad + i * 4096, as + (size_t)i * 4096);             \
            CP_ASYNC16(bd + i * 4096, bs + (size_t)i * 4096);             \
        }                                                                 \
        CP_COMMIT();                                                      \
    }

    STAGE_CP(0, 0)
    STAGE_CP(1, 1)

    for (int it = 0; it < NCHK; it++) {
        if (it + 2 < NCHK) { CP_WAIT1(); } else { CP_WAIT0(); }
        __syncthreads();
        uint32_t sa = sbase + (it & 1) * STAGE_BYTES;
        uint32_t sb = sa + 16384;
#pragma unroll
        for (int k8 = 0; k8 < 4; k8++) {
            unsigned af[2][4], bf[4][4];
#pragma unroll
            for (int mi = 0; mi < 2; mi++) {
                uint32_t a = sa + (uint32_t)(((k8 * 8 + mb16 + mi) * 32 + lane) * 16);
                LDS128(af[mi][0], af[mi][1], af[mi][2], af[mi][3], a);
            }
#pragma unroll
            for (int j = 0; j < 4; j++) {
                uint32_t a = sb + (uint32_t)(((k8 * 8 + nb16 + j) * 32 + lane) * 16);
                LDS128(bf[j][0], bf[j][1], bf[j][2], bf[j][3], a);
            }
#pragma unroll
            for (int mi = 0; mi < 2; mi++)
#pragma unroll
                for (int j = 0; j < 4; j++) {
                    mma_tf32(acc[mi][2 * j],     af[mi], bf[j][0], bf[j][1]);
                    mma_tf32(acc[mi][2 * j + 1], af[mi], bf[j][2], bf[j][3]);
                }
        }
        __syncthreads();
        if (it + 2 < NCHK) STAGE_CP(it & 1, it + 2)
    }

    const int brow = mtile * 128, bcol = ntile * 128;
    const int wm = (wid & 3) * 32, wn = (wid >> 2) * 64;
#pragma unroll
    for (int mi = 0; mi < 2; mi++) {
#pragma unroll
        for (int nj = 0; nj < 8; nj++) {
            int r = brow + wm + mi * 16 + g;
            int c = bcol + wn + nj * 8 + 2 * tg;
            if (r < M)
                *(float2*)&Cm[(size_t)r * HC + c] =
                    make_float2(acc[mi][nj][0], acc[mi][nj][1]);
            if (r + 8 < M)
                *(float2*)&Cm[(size_t)(r + 8) * HC + c] =
                    make_float2(acc[mi][nj][2], acc[mi][nj][3]);
        }
    }
#undef STAGE_CP
}

// ---------------- fused score weights: Wsd[j][k] ------------------------------
// Wsd[h][k]    = sum_c W[k, h*C+c] * a_src[h][c]
// Wsd[12+h][k] = sum_c W[k, h*C+c] * a_dst[h][c]
__global__ __launch_bounds__(384)
void ws_kernel(const float* __restrict__ W, const float* __restrict__ a_src,
               const float* __restrict__ a_dst) {
    int k = blockIdx.x;                  // 0..767
    int h = threadIdx.x >> 5;            // 0..11
    int lane = threadIdx.x & 31;
    const float* wr = &W[(size_t)k * HC + h * CC];
    const float* as = &a_src[h * CC];
    const float* ad = &a_dst[h * CC];
    float ps = 0.f, pd = 0.f;
#pragma unroll
    for (int i = 0; i < CC / 32; i++) {
        float v = wr[i * 32 + lane];
        ps += v * as[i * 32 + lane];
        pd += v * ad[i * 32 + lane];
    }
    for (int o = 16; o; o >>= 1) {
        ps += __shfl_xor_sync(0xffffffffu, ps, o);
        pd += __shfl_xor_sync(0xffffffffu, pd, o);
    }
    if (lane == 0) {
        g_Wsd[h * CC + k]        = ps;
        g_Wsd[(12 + h) * CC + k] = pd;
    }
}

// ---------------- node scores: s/d[n][h] = sum_k A[n][k] * Wsd[j][k] ---------
__global__ __launch_bounds__(256)
void nodescore_kernel(const float* __restrict__ A) {
    extern __shared__ float sw[];        // [24][768]
    int tid = threadIdx.x, wid = tid >> 5, lane = tid & 31;
#pragma unroll
    for (int i = 0; i < 18; i++) {
        int idx = tid * 4 + i * 1024;    // 18 float4 per thread = 18432 floats
        *(float4*)&sw[idx] = *(const float4*)&g_Wsd[idx];
    }
    __syncthreads();
    int n = blockIdx.x * 8 + wid;
    const float* Ar = &A[(size_t)n * CC];
    float ps[HH], pd[HH];
#pragma unroll
    for (int h = 0; h < HH; h++) { ps[h] = 0.f; pd[h] = 0.f; }
#pragma unroll 4
    for (int i = 0; i < CC / 32; i++) {
        int k = i * 32 + lane;
        float av = Ar[k];
#pragma unroll
        for (int h = 0; h < HH; h++) {
            ps[h] += av * sw[h * CC + k];
            pd[h] += av * sw[(12 + h) * CC + k];
        }
    }
#pragma unroll
    for (int h = 0; h < HH; h++) {
        for (int o = 16; o; o >>= 1) {
            ps[h] += __shfl_xor_sync(0xffffffffu, ps[h], o);
            pd[h] += __shfl_xor_sync(0xffffffffu, pd[h], o);
        }
    }
    if (lane < HH) {
        g_s[n * HH + lane] = ps[0];
        g_d[n * HH + lane] = pd[0];
    }
    // lane-indexed write needs values gathered: redo properly below
    if (lane == 0) {
#pragma unroll
        for (int h = 0; h < HH; h++) {
            g_s[n * HH + h] = ps[h];
            g_d[n * HH + h] = pd[h];
        }
    }
}

// ---------------- segment softmax (one warp per destination node) ----------
__global__ void softmax_kernel() {
    int warp = (blockIdx.x * blockDim.x + threadIdx.x) >> 5;
    int lane = threadIdx.x & 31;
    if (warp >= NN) return;
    int n  = warp;
    int r0 = g_rowptr[n], r1 = g_rowptr[n + 1];
    for (int h = 0; h < HH; h++) {
        float dn = g_d[n * HH + h];
        float mx = -1e30f;
        for (int p = r0 + lane; p < r1; p += 32) {
            float v = g_s[g_ssrc[p] * HH + h] + dn;
            v = (v > 0.f) ? v : 0.2f * v;
            mx = fmaxf(mx, v);
        }
        for (int o = 16; o; o >>= 1) mx = fmaxf(mx, __shfl_xor_sync(0xffffffffu, mx, o));
        float sum = 0.f;
        for (int p = r0 + lane; p < r1; p += 32) {
            float v = g_s[g_ssrc[p] * HH + h] + dn;
            v = (v > 0.f) ? v : 0.2f * v;
            float ex = __expf(v - mx);
            g_alpha[p * HH + h] = ex;
            sum += ex;
        }
        for (int o = 16; o; o >>= 1) sum += __shfl_xor_sync(0xffffffffu, sum, o);
        float inv = 1.f / (sum + 1e-16f);
        for (int p = r0 + lane; p < r1; p += 32) g_alpha[p * HH + h] *= inv;
    }
}

// ---------------- aggregation + head mean + bias (block per node) ----------
// vectorized float4 gather; per-quad alpha via __ldg; head mean via smem pass
__global__ __launch_bounds__(256)
void aggregate_kernel(const float* __restrict__ bias, float* __restrict__ out) {
    __shared__ float sm[HC];             // 36 KB
    int n   = blockIdx.x;
    int tid = threadIdx.x;
    float4 acc[9];
#pragma unroll
    for (int q = 0; q < 9; q++) acc[q] = make_float4(0.f, 0.f, 0.f, 0.f);
    int r0 = g_rowptr[n], r1 = g_rowptr[n + 1];
    for (int p = r0; p < r1; p++) {
        const float4* hp = (const float4*)&g_h[(size_t)g_ssrc[p] * HC];
        const float*  ap = &g_alpha[p * HH];
#pragma unroll
        for (int q = 0; q < 9; q++) {
            int qg = q * 256 + tid;                 // quad index 0..2303
            float a = __ldg(&ap[qg / 192]);         // head = qg/192, L1 broadcast
            float4 v = __ldg(&hp[qg]);
            acc[q].x += a * v.x; acc[q].y += a * v.y;
            acc[q].z += a * v.z; acc[q].w += a * v.w;
        }
    }
#pragma unroll
    for (int q = 0; q < 9; q++)
        *(float4*)&sm[(q * 256 + tid) * 4] = acc[q];
    __syncthreads();
    const float invH = 1.0f / (float)HH;
#pragma unroll
    for (int r = 0; r < 3; r++) {
        int c = tid + r * 256;
        float v = 0.f;
#pragma unroll
        for (int h = 0; h < HH; h++) v += sm[h * CC + c];
        out[(size_t)n * CC + c] = v * invH + bias[c];
    }
}

// ---------------- pooling: contiguous segment sum (batch sorted) -------------
__global__ __launch_bounds__(128)
void pool_sum_kernel(const float* __restrict__ xin) {
    int gid = blockIdx.x;                // graph
    int col = blockIdx.y * 128 + threadIdx.x;
    int start = g_gstart[gid], cnt = g_cnt[gid];
    float s = 0.f;
    for (int i = 0; i < cnt; i++)
        s += xin[(size_t)(start + i) * CC + col];
    g_pool[gid * CC + col] = s;
}

// ---------------- final MLP (block per graph) -------------------------------
__global__ __launch_bounds__(128)
void mlp_kernel(const float* __restrict__ w1, const float* __restrict__ b1,
                const float* __restrict__ w2, const float* __restrict__ b2,
                float* __restrict__ out) {
    int gid = blockIdx.x;     // 0..63
    int tid = threadIdx.x;    // 128
    __shared__ float gv[CC];
    __shared__ float z[128];
    float invc = 1.0f / fmaxf((float)g_cnt[gid], 1.0f);
    for (int c = tid; c < CC; c += 128) gv[c] = g_pool[gid * CC + c] * invc;
    __syncthreads();
    float acc = b1[tid];
    for (int k = 0; k < CC; k++) acc += gv[k] * w1[k * 128 + tid];
    z[tid] = fmaxf(acc, 0.f);
    __syncthreads();
    if (tid < 4) {
        float o = b2[tid];
        for (int j = 0; j < 128; j++) o += z[j] * w2[j * 4 + tid];
        out[gid * 4 + tid] = o;
    }
}

// ---------------- launcher ---------------------------------------------------
extern "C" void kernel_launch(void* const* d_in, const int* in_sizes, int n_in,
                              void* d_out, int out_size) {
    const float* x        = (const float*)d_in[0];
    const int*   eidx     = (const int*)  d_in[1];
    const int*   batch    = (const int*)  d_in[2];
    const float* W1       = (const float*)d_in[3];
    const float* a_src1   = (const float*)d_in[4];
    const float* a_dst1   = (const float*)d_in[5];
    const float* b1       = (const float*)d_in[6];
    const float* W2       = (const float*)d_in[7];
    const float* a_src2   = (const float*)d_in[8];
    const float* a_dst2   = (const float*)d_in[9];
    const float* b2       = (const float*)d_in[10];
    const float* mlp_w1   = (const float*)d_in[11];
    const float* mlp_b1   = (const float*)d_in[12];
    const float* mlp_w2   = (const float*)d_in[13];
    const float* mlp_b2   = (const float*)d_in[14];
    float* out = (float*)d_out;

    float *p_h, *p_x2, *p_y;
    cudaGetSymbolAddress((void**)&p_h,  g_h);
    cudaGetSymbolAddress((void**)&p_x2, g_x2);
    cudaGetSymbolAddress((void**)&p_y,  g_y);

    const int gemm_smem = 2 * STAGE_BYTES;     // 65536
    cudaFuncSetAttribute(frag_gemm_kernel,
                         cudaFuncAttributeMaxDynamicSharedMemorySize, gemm_smem);
    const int ns_smem = 24 * CC * 4;           // 73728
    cudaFuncSetAttribute(nodescore_kernel,
                         cudaFuncAttributeMaxDynamicSharedMemorySize, ns_smem);

    // --- CSR build + graph segments (identical every call; cheap) ---
    zero_build_kernel<<<(NN + 255) / 256, 256>>>();
    count_deg_kernel<<<(ETOT + 255) / 256, 256>>>(eidx);
    scan_kernel<<<1, 1024>>>();
    fill_csr_kernel<<<(ETOT + 255) / 256, 256>>>(eidx);
    graph_start_kernel<<<(NN + 255) / 256, 256>>>(batch);

    dim3 pa_grid(MTILES, 12);
    dim3 pb_grid(NTILES, 12);
    dim3 ggrid(NTILES, MTILES);

    // --- GAT layer 1 ---
    prep_A_kernel<<<pa_grid, 256>>>(x, NN);
    prep_B_kernel<<<pb_grid, 256>>>(W1);
    frag_gemm_kernel<<<ggrid, 256, gemm_smem>>>(p_h, NN);
    ws_kernel<<<CC, 384>>>(W1, a_src1, a_dst1);
    nodescore_kernel<<<NN / 8, 256, ns_smem>>>(x);
    softmax_kernel<<<(NN * 32 + 255) / 256, 256>>>();
    aggregate_kernel<<<NN, 256>>>(b1, p_x2);

    // --- GAT layer 2 ---
    prep_A_kernel<<<pa_grid, 256>>>(p_x2, NN);
    prep_B_kernel<<<pb_grid, 256>>>(W2);
    frag_gemm_kernel<<<ggrid, 256, gemm_smem>>>(p_h, NN);
    ws_kernel<<<CC, 384>>>(W2, a_src2, a_dst2);
    nodescore_kernel<<<NN / 8, 256, ns_smem>>>(p_x2);
    softmax_kernel<<<(NN * 32 + 255) / 256, 256>>>();
    aggregate_kernel<<<NN, 256>>>(b2, p_y);

    // --- pooling + MLP ---
    pool_sum_kernel<<<dim3(GGR, CC / 128), 128>>>(p_y);
    mlp_kernel<<<GGR, 128>>>(mlp_w1, mlp_b1, mlp_w2, mlp_b2, out);
}

// round 6
// speedup vs baseline: 1.6576x; 1.6576x over previous
#include <cuda_runtime.h>
#include <cuda_fp16.h>
#include <cstdint>

// Problem constants
#define NN   10000          // nodes
#define EE   20000          // edges (without self loops)
#define ETOT 30000          // edges + self loops
#define HH   12             // heads
#define CC   768            // per-head dim (== input feature dim)
#define HC   9216           // H*C
#define GGR  64             // graphs

#define MTILES 79           // ceil(10000/128)
#define NTILES 72           // 9216/128
#define KB16   48           // 768/16 k-blocks
// fp16 fragment tile: 48 kb16 x 8 blk16 x 32 lanes x 16B = 196608 bytes
#define FRAG_TILE_BYTES 196608

// ---------------- device scratch (static globals; no runtime alloc) --------
__device__ float g_h[(size_t)NN * HC];     // per-layer node features [N, H*C]
__device__ float g_x2[NN * CC];            // layer-1 output / layer-2 input
__device__ float g_y[NN * CC];             // layer-2 output
__device__ uint4 g_Afrag[(size_t)MTILES * FRAG_TILE_BYTES / 16];
__device__ uint4 g_Bfrag[(size_t)NTILES * FRAG_TILE_BYTES / 16];
__device__ float g_Wsd[24 * CC];           // fused score weights [24][768]
__device__ float g_s[NN * HH];             // alpha_src per node/head
__device__ float g_d[NN * HH];             // alpha_dst per node/head
__device__ float g_alpha[ETOT * HH];       // softmax weights (pre-scaled by 1/H)
__device__ int   g_indeg[NN];
__device__ int   g_outdeg[NN];
__device__ int   g_rowptr[NN + 1];         // dst CSR
__device__ int   g_srowptr[NN + 1];        // src CSR
__device__ int   g_fill[NN];
__device__ int   g_sfill[NN];
__device__ int   g_ssrc[ETOT];             // src node per dst-CSR position
__device__ int   g_sdst[ETOT];             // dst node per src-CSR position
__device__ int   g_sapos[ETOT];            // alpha (dst-CSR) position per src-CSR pos
__device__ float g_pool[GGR * CC];
__device__ int   g_cnt[GGR];
__device__ int   g_gstart[GGR];

// ---------------- helpers ----------------------------------------------------
__device__ __forceinline__ uint32_t smem_u32(const void* p) {
    uint32_t a;
    asm("{ .reg .u64 t; cvta.to.shared.u64 t, %1; cvt.u32.u64 %0, t; }"
        : "=r"(a) : "l"(p));
    return a;
}

__device__ __forceinline__ unsigned pack2(float lo, float hi) {
    __half2 h = __floats2half2_rn(lo, hi);
    return *reinterpret_cast<unsigned*>(&h);
}

__device__ __forceinline__ void mma_fp16(float* d, const unsigned* a,
                                         unsigned b0, unsigned b1) {
    asm volatile(
        "mma.sync.aligned.m16n8k16.row.col.f32.f16.f16.f32 "
        "{%0,%1,%2,%3}, {%4,%5,%6,%7}, {%8,%9}, {%0,%1,%2,%3};\n"
        : "+f"(d[0]), "+f"(d[1]), "+f"(d[2]), "+f"(d[3])
        : "r"(a[0]), "r"(a[1]), "r"(a[2]), "r"(a[3]), "r"(b0), "r"(b1));
}

#define CP_ASYNC16(dst, src) \
    asm volatile("cp.async.cg.shared.global [%0], [%1], 16;" :: \
                 "r"(dst), "l"(src) : "memory")
#define CP_COMMIT() asm volatile("cp.async.commit_group;" ::: "memory")
#define CP_WAIT1()  asm volatile("cp.async.wait_group 1;" ::: "memory")
#define CP_WAIT0()  asm volatile("cp.async.wait_group 0;" ::: "memory")

#define LDS128(r0, r1, r2, r3, addr) \
    asm volatile("ld.shared.v4.b32 {%0,%1,%2,%3}, [%4];" \
                 : "=r"(r0), "=r"(r1), "=r"(r2), "=r"(r3) : "r"(addr))

// ---------------- CSR build ------------------------------------------------
__global__ void zero_build_kernel() {
    int i = blockIdx.x * blockDim.x + threadIdx.x;
    if (i < NN) { g_indeg[i] = 0; g_fill[i] = 0; g_outdeg[i] = 0; g_sfill[i] = 0; }
    if (i < GGR) { g_cnt[i] = 0; g_gstart[i] = NN; }
}

__global__ void count_deg_kernel(const int* __restrict__ edge_index) {
    int e = blockIdx.x * blockDim.x + threadIdx.x;
    if (e >= ETOT) return;
    int src = (e < EE) ? edge_index[e]      : (e - EE);
    int dst = (e < EE) ? edge_index[EE + e] : (e - EE);
    atomicAdd(&g_indeg[dst], 1);
    atomicAdd(&g_outdeg[src], 1);
}

__global__ void scan_kernel(const int* __restrict__ deg, int* __restrict__ rowptr) {
    __shared__ int sd[1024];
    __shared__ int soff;
    int t = threadIdx.x;
    if (t == 0) { soff = 0; rowptr[0] = 0; }
    __syncthreads();
    for (int base = 0; base < NN; base += 1024) {
        int i = base + t;
        int v = (i < NN) ? deg[i] : 0;
        sd[t] = v;
        __syncthreads();
        for (int off = 1; off < 1024; off <<= 1) {
            int tmp = (t >= off) ? sd[t - off] : 0;
            __syncthreads();
            sd[t] += tmp;
            __syncthreads();
        }
        if (i < NN) rowptr[i + 1] = soff + sd[t];
        __syncthreads();
        if (t == 0) soff += sd[1023];
        __syncthreads();
    }
}

__global__ void fill_both_kernel(const int* __restrict__ edge_index) {
    int e = blockIdx.x * blockDim.x + threadIdx.x;
    if (e >= ETOT) return;
    int src = (e < EE) ? edge_index[e]      : (e - EE);
    int dst = (e < EE) ? edge_index[EE + e] : (e - EE);
    int pd = g_rowptr[dst] + atomicAdd(&g_fill[dst], 1);
    g_ssrc[pd] = src;
    int ps = g_srowptr[src] + atomicAdd(&g_sfill[src], 1);
    g_sdst[ps]  = dst;
    g_sapos[ps] = pd;
}

__global__ void graph_start_kernel(const int* __restrict__ batch) {
    int n = blockIdx.x * blockDim.x + threadIdx.x;
    if (n < NN) {
        atomicMin(&g_gstart[batch[n]], n);
        atomicAdd(&g_cnt[batch[n]], 1);
    }
}

// ---------------- fp16 fragment packing --------------------------------------
// A_frag: [mtile][kb16][m16 0..7][lane] uint4 = a0..a3 of m16n8k16 row-major A
__global__ __launch_bounds__(256)
void prep_A_kernel(const float* __restrict__ src, int M) {
    __shared__ float st[128 * 68];       // 128 rows x 64 k, pitch 68
    int tid = threadIdx.x, lane = tid & 31, wid = tid >> 5;
    int mtile = blockIdx.x, kgrp = blockIdx.y;   // kgrp covers 64 k
#pragma unroll
    for (int i = 0; i < 8; i++) {
        int idx = tid + i * 256;
        int row = idx >> 4, c4 = idx & 15;
        int m = mtile * 128 + row;
        float4 v = make_float4(0.f, 0.f, 0.f, 0.f);
        if (m < M) v = *(const float4*)&src[(size_t)m * CC + kgrp * 64 + c4 * 4];
        *(float4*)&st[row * 68 + c4 * 4] = v;
    }
    __syncthreads();
    int g = lane >> 2, tg = lane & 3;
#pragma unroll
    for (int t = 0; t < 4; t++) {
        int fb  = wid * 4 + t;           // 0..31
        int kbl = fb & 3, m16 = fb >> 2;
        int r0 = m16 * 16 + g, r1 = r0 + 8;
        int k0 = kbl * 16 + 2 * tg;
        uint4 o;
        o.x = pack2(st[r0 * 68 + k0],     st[r0 * 68 + k0 + 1]);
        o.y = pack2(st[r1 * 68 + k0],     st[r1 * 68 + k0 + 1]);
        o.z = pack2(st[r0 * 68 + k0 + 8], st[r0 * 68 + k0 + 9]);
        o.w = pack2(st[r1 * 68 + k0 + 8], st[r1 * 68 + k0 + 9]);
        g_Afrag[(size_t)(mtile * KB16 + kgrp * 4 + kbl) * 256 + m16 * 32 + lane] = o;
    }
}

// B_frag: [ntile][kb16][n16 0..7][lane] uint4 = {b0,b1 even n8, b0,b1 odd n8}
__global__ __launch_bounds__(256)
void prep_B_kernel(const float* __restrict__ W) {
    __shared__ float st[64 * 132];       // 64 k x 128 n, pitch 132
    int tid = threadIdx.x, lane = tid & 31, wid = tid >> 5;
    int ntile = blockIdx.x, kgrp = blockIdx.y;
#pragma unroll
    for (int i = 0; i < 8; i++) {
        int idx = tid + i * 256;
        int row = idx >> 5, c4 = idx & 31;
        float4 v = *(const float4*)&W[(size_t)(kgrp * 64 + row) * HC +
                                      ntile * 128 + c4 * 4];
        *(float4*)&st[row * 132 + c4 * 4] = v;
    }
    __syncthreads();
    int g = lane >> 2, tg = lane & 3;
#pragma unroll
    for (int t = 0; t < 4; t++) {
        int fb  = wid * 4 + t;
        int kbl = fb & 3, n16 = fb >> 2;
        int k0 = kbl * 16 + 2 * tg;
        int ne = n16 * 16 + g, no = ne + 8;
        uint4 o;
        o.x = pack2(st[k0 * 132 + ne],       st[(k0 + 1) * 132 + ne]);
        o.y = pack2(st[(k0 + 8) * 132 + ne], st[(k0 + 9) * 132 + ne]);
        o.z = pack2(st[k0 * 132 + no],       st[(k0 + 1) * 132 + no]);
        o.w = pack2(st[(k0 + 8) * 132 + no], st[(k0 + 9) * 132 + no]);
        g_Bfrag[(size_t)(ntile * KB16 + kgrp * 4 + kbl) * 256 + n16 * 32 + lane] = o;
    }
}

// ---------------- fp16 fragment GEMM -----------------------------------------
// K-chunk = 64 (4 kb16), 12 chunks, 2-stage cp.async, 32KB per stage.
#define NCHK 12
#define STAGE_BYTES 32768    // 16KB A + 16KB B

__global__ __launch_bounds__(256)
void frag_gemm_kernel(float* __restrict__ Cm, int M) {
    extern __shared__ char smem[];
    const uint32_t sbase = smem_u32(smem);
    const int tid = threadIdx.x, wid = tid >> 5, lane = tid & 31;
    const int mtile = blockIdx.y, ntile = blockIdx.x;
    const char* Abase = (const char*)g_Afrag + (size_t)mtile * FRAG_TILE_BYTES;
    const char* Bbase = (const char*)g_Bfrag + (size_t)ntile * FRAG_TILE_BYTES;

    const int g = lane >> 2, tg = lane & 3;
    const int mb16 = (wid & 3) * 2;      // 2 m16 blocks per warp
    const int nb16 = (wid >> 2) * 4;     // 4 n16 blocks per warp

    float acc[2][8][4];
#pragma unroll
    for (int i = 0; i < 2; i++)
#pragma unroll
        for (int j = 0; j < 8; j++)
#pragma unroll
            for (int q = 0; q < 4; q++) acc[i][j][q] = 0.f;

#define STAGE_CP(buf, chunk)                                              \
    {                                                                     \
        const char* as = Abase + (size_t)(chunk) * 16384 + tid * 16;      \
        const char* bs = Bbase + (size_t)(chunk) * 16384 + tid * 16;      \
        uint32_t ad = sbase + (buf) * STAGE_BYTES + tid * 16;             \
        uint32_t bd = ad + 16384;                                         \
        _Pragma("unroll")                                                 \
        for (int i = 0; i < 4; i++) {                                     \
            CP_ASYNC16(ad + i * 4096, as + (size_t)i * 4096);             \
            CP_ASYNC16(bd + i * 4096, bs + (size_t)i * 4096);             \
        }                                                                 \
        CP_COMMIT();                                                      \
    }

    STAGE_CP(0, 0)
    STAGE_CP(1, 1)

    for (int it = 0; it < NCHK; it++) {
        if (it + 2 < NCHK) { CP_WAIT1(); } else { CP_WAIT0(); }
        __syncthreads();
        uint32_t sa = sbase + (it & 1) * STAGE_BYTES;
        uint32_t sb = sa + 16384;
#pragma unroll
        for (int kbl = 0; kbl < 4; kbl++) {
            unsigned af[2][4], bf[4][4];
#pragma unroll
            for (int mi = 0; mi < 2; mi++) {
                uint32_t a = sa + (uint32_t)(((kbl * 8 + mb16 + mi) * 32 + lane) * 16);
                LDS128(af[mi][0], af[mi][1], af[mi][2], af[mi][3], a);
            }
#pragma unroll
            for (int j = 0; j < 4; j++) {
                uint32_t a = sb + (uint32_t)(((kbl * 8 + nb16 + j) * 32 + lane) * 16);
                LDS128(bf[j][0], bf[j][1], bf[j][2], bf[j][3], a);
            }
#pragma unroll
            for (int mi = 0; mi < 2; mi++)
#pragma unroll
                for (int j = 0; j < 4; j++) {
                    mma_fp16(acc[mi][2 * j],     af[mi], bf[j][0], bf[j][1]);
                    mma_fp16(acc[mi][2 * j + 1], af[mi], bf[j][2], bf[j][3]);
                }
        }
        __syncthreads();
        if (it + 2 < NCHK) STAGE_CP(it & 1, it + 2)
    }

    const int brow = mtile * 128, bcol = ntile * 128;
    const int wm = (wid & 3) * 32, wn = (wid >> 2) * 64;
#pragma unroll
    for (int mi = 0; mi < 2; mi++) {
#pragma unroll
        for (int nj = 0; nj < 8; nj++) {
            int r = brow + wm + mi * 16 + g;
            int c = bcol + wn + nj * 8 + 2 * tg;
            if (r < M)
                *(float2*)&Cm[(size_t)r * HC + c] =
                    make_float2(acc[mi][nj][0], acc[mi][nj][1]);
            if (r + 8 < M)
                *(float2*)&Cm[(size_t)(r + 8) * HC + c] =
                    make_float2(acc[mi][nj][2], acc[mi][nj][3]);
        }
    }
#undef STAGE_CP
}

// ---------------- fused score weights: Wsd[j][k] ------------------------------
__global__ __launch_bounds__(384)
void ws_kernel(const float* __restrict__ W, const float* __restrict__ a_src,
               const float* __restrict__ a_dst) {
    int k = blockIdx.x;
    int h = threadIdx.x >> 5;
    int lane = threadIdx.x & 31;
    const float* wr = &W[(size_t)k * HC + h * CC];
    const float* as = &a_src[h * CC];
    const float* ad = &a_dst[h * CC];
    float ps = 0.f, pd = 0.f;
#pragma unroll
    for (int i = 0; i < CC / 32; i++) {
        float v = wr[i * 32 + lane];
        ps += v * as[i * 32 + lane];
        pd += v * ad[i * 32 + lane];
    }
    for (int o = 16; o; o >>= 1) {
        ps += __shfl_xor_sync(0xffffffffu, ps, o);
        pd += __shfl_xor_sync(0xffffffffu, pd, o);
    }
    if (lane == 0) {
        g_Wsd[h * CC + k]        = ps;
        g_Wsd[(12 + h) * CC + k] = pd;
    }
}

// ---------------- node scores: s/d[n][h] = sum_k A[n][k] * Wsd[j][k] ---------
__global__ __launch_bounds__(256)
void nodescore_kernel(const float* __restrict__ A) {
    extern __shared__ float sw[];        // [24][768]
    int tid = threadIdx.x, wid = tid >> 5, lane = tid & 31;
#pragma unroll
    for (int i = 0; i < 18; i++) {
        int idx = tid * 4 + i * 1024;
        *(float4*)&sw[idx] = *(const float4*)&g_Wsd[idx];
    }
    __syncthreads();
    int n = blockIdx.x * 8 + wid;
    const float* Ar = &A[(size_t)n * CC];
    float ps[HH], pd[HH];
#pragma unroll
    for (int h = 0; h < HH; h++) { ps[h] = 0.f; pd[h] = 0.f; }
#pragma unroll 4
    for (int i = 0; i < CC / 32; i++) {
        int k = i * 32 + lane;
        float av = Ar[k];
#pragma unroll
        for (int h = 0; h < HH; h++) {
            ps[h] += av * sw[h * CC + k];
            pd[h] += av * sw[(12 + h) * CC + k];
        }
    }
#pragma unroll
    for (int h = 0; h < HH; h++) {
        for (int o = 16; o; o >>= 1) {
            ps[h] += __shfl_xor_sync(0xffffffffu, ps[h], o);
            pd[h] += __shfl_xor_sync(0xffffffffu, pd[h], o);
        }
    }
    if (lane == 0) {
#pragma unroll
        for (int h = 0; h < HH; h++) {
            g_s[n * HH + h] = ps[h];
            g_d[n * HH + h] = pd[h];
        }
    }
}

// ---------------- segment softmax (one warp per destination node) ----------
// alpha pre-scaled by 1/H for the head-mean epilogue
__global__ void softmax_kernel() {
    int warp = (blockIdx.x * blockDim.x + threadIdx.x) >> 5;
    int lane = threadIdx.x & 31;
    if (warp >= NN) return;
    int n  = warp;
    int r0 = g_rowptr[n], r1 = g_rowptr[n + 1];
    for (int h = 0; h < HH; h++) {
        float dn = g_d[n * HH + h];
        float mx = -1e30f;
        for (int p = r0 + lane; p < r1; p += 32) {
            float v = g_s[g_ssrc[p] * HH + h] + dn;
            v = (v > 0.f) ? v : 0.2f * v;
            mx = fmaxf(mx, v);
        }
        for (int o = 16; o; o >>= 1) mx = fmaxf(mx, __shfl_xor_sync(0xffffffffu, mx, o));
        float sum = 0.f;
        for (int p = r0 + lane; p < r1; p += 32) {
            float v = g_s[g_ssrc[p] * HH + h] + dn;
            v = (v > 0.f) ? v : 0.2f * v;
            float ex = __expf(v - mx);
            g_alpha[p * HH + h] = ex;
            sum += ex;
        }
        for (int o = 16; o; o >>= 1) sum += __shfl_xor_sync(0xffffffffu, sum, o);
        float inv = 1.f / ((float)HH * (sum + 1e-16f));
        for (int p = r0 + lane; p < r1; p += 32) g_alpha[p * HH + h] *= inv;
    }
}

// ---------------- scatter aggregation ----------------------------------------
__global__ void init_out_kernel(const float* __restrict__ bias,
                                float* __restrict__ out) {
    int i = blockIdx.x * blockDim.x + threadIdx.x;   // float4 index
    if (i >= NN * CC / 4) return;
    int c4 = i % (CC / 4);
    ((float4*)out)[i] = ((const float4*)bias)[c4];
}

// one block per source node: read row once, scatter alpha-weighted 768-dim
// head-mean contribution to each out-neighbor via atomics.
__global__ __launch_bounds__(256)
void scatter_agg_kernel(float* __restrict__ out) {
    __shared__ float row[HC];            // 36 KB
    int n   = blockIdx.x;
    int tid = threadIdx.x;
    const float4* hp = (const float4*)&g_h[(size_t)n * HC];
#pragma unroll
    for (int q = 0; q < 9; q++)
        *(float4*)&row[(q * 256 + tid) * 4] = hp[q * 256 + tid];
    int r0 = g_srowptr[n], r1 = g_srowptr[n + 1];
    __syncthreads();
    for (int p = r0; p < r1; p++) {
        int dst  = g_sdst[p];
        int apos = g_sapos[p];
        const float4* ap = (const float4*)&g_alpha[apos * HH];
        float4 a0 = __ldg(&ap[0]);
        float4 a1 = __ldg(&ap[1]);
        float4 a2 = __ldg(&ap[2]);
        float al[HH] = {a0.x, a0.y, a0.z, a0.w, a1.x, a1.y, a1.z, a1.w,
                        a2.x, a2.y, a2.z, a2.w};
        float* op = &out[(size_t)dst * CC];
#pragma unroll
        for (int r = 0; r < 3; r++) {
            int c = tid + r * 256;
            float v = 0.f;
#pragma unroll
            for (int h = 0; h < HH; h++) v += al[h] * row[h * CC + c];
            atomicAdd(&op[c], v);
        }
    }
}

// ---------------- pooling: contiguous segment sum (batch sorted) -------------
__global__ __launch_bounds__(128)
void pool_sum_kernel(const float* __restrict__ xin) {
    int gid = blockIdx.x;
    int col = blockIdx.y * 128 + threadIdx.x;
    int start = g_gstart[gid], cnt = g_cnt[gid];
    float s = 0.f;
    for (int i = 0; i < cnt; i++)
        s += xin[(size_t)(start + i) * CC + col];
    g_pool[gid * CC + col] = s;
}

// ---------------- final MLP (block per graph) -------------------------------
__global__ __launch_bounds__(128)
void mlp_kernel(const float* __restrict__ w1, const float* __restrict__ b1,
                const float* __restrict__ w2, const float* __restrict__ b2,
                float* __restrict__ out) {
    int gid = blockIdx.x;
    int tid = threadIdx.x;
    __shared__ float gv[CC];
    __shared__ float z[128];
    float invc = 1.0f / fmaxf((float)g_cnt[gid], 1.0f);
    for (int c = tid; c < CC; c += 128) gv[c] = g_pool[gid * CC + c] * invc;
    __syncthreads();
    float acc = b1[tid];
    for (int k = 0; k < CC; k++) acc += gv[k] * w1[k * 128 + tid];
    z[tid] = fmaxf(acc, 0.f);
    __syncthreads();
    if (tid < 4) {
        float o = b2[tid];
        for (int j = 0; j < 128; j++) o += z[j] * w2[j * 4 + tid];
        out[gid * 4 + tid] = o;
    }
}

// ---------------- launcher ---------------------------------------------------
extern "C" void kernel_launch(void* const* d_in, const int* in_sizes, int n_in,
                              void* d_out, int out_size) {
    const float* x        = (const float*)d_in[0];
    const int*   eidx     = (const int*)  d_in[1];
    const int*   batch    = (const int*)  d_in[2];
    const float* W1       = (const float*)d_in[3];
    const float* a_src1   = (const float*)d_in[4];
    const float* a_dst1   = (const float*)d_in[5];
    const float* b1       = (const float*)d_in[6];
    const float* W2       = (const float*)d_in[7];
    const float* a_src2   = (const float*)d_in[8];
    const float* a_dst2   = (const float*)d_in[9];
    const float* b2       = (const float*)d_in[10];
    const float* mlp_w1   = (const float*)d_in[11];
    const float* mlp_b1   = (const float*)d_in[12];
    const float* mlp_w2   = (const float*)d_in[13];
    const float* mlp_b2   = (const float*)d_in[14];
    float* out = (float*)d_out;

    float *p_h, *p_x2, *p_y;
    int *p_indeg, *p_outdeg, *p_rowptr, *p_srowptr;
    cudaGetSymbolAddress((void**)&p_h,  g_h);
    cudaGetSymbolAddress((void**)&p_x2, g_x2);
    cudaGetSymbolAddress((void**)&p_y,  g_y);
    cudaGetSymbolAddress((void**)&p_indeg,   g_indeg);
    cudaGetSymbolAddress((void**)&p_outdeg,  g_outdeg);
    cudaGetSymbolAddress((void**)&p_rowptr,  g_rowptr);
    cudaGetSymbolAddress((void**)&p_srowptr, g_srowptr);

    const int gemm_smem = 2 * STAGE_BYTES;     // 65536
    cudaFuncSetAttribute(frag_gemm_kernel,
                         cudaFuncAttributeMaxDynamicSharedMemorySize, gemm_smem);
    const int ns_smem = 24 * CC * 4;           // 73728
    cudaFuncSetAttribute(nodescore_kernel,
                         cudaFuncAttributeMaxDynamicSharedMemorySize, ns_smem);

    // --- CSR build (dst + src) + graph segments ---
    zero_build_kernel<<<(NN + 255) / 256, 256>>>();
    count_deg_kernel<<<(ETOT + 255) / 256, 256>>>(eidx);
    scan_kernel<<<1, 1024>>>(p_indeg,  p_rowptr);
    scan_kernel<<<1, 1024>>>(p_outdeg, p_srowptr);
    fill_both_kernel<<<(ETOT + 255) / 256, 256>>>(eidx);
    graph_start_kernel<<<(NN + 255) / 256, 256>>>(batch);

    dim3 pa_grid(MTILES, 12);
    dim3 pb_grid(NTILES, 12);
    dim3 ggrid(NTILES, MTILES);

    // --- GAT layer 1 ---
    prep_A_kernel<<<pa_grid, 256>>>(x, NN);
    prep_B_kernel<<<pb_grid, 256>>>(W1);
    frag_gemm_kernel<<<ggrid, 256, gemm_smem>>>(p_h, NN);
    ws_kernel<<<CC, 384>>>(W1, a_src1, a_dst1);
    nodescore_kernel<<<NN / 8, 256, ns_smem>>>(x);
    softmax_kernel<<<(NN * 32 + 255) / 256, 256>>>();
    init_out_kernel<<<(NN * CC / 4 + 255) / 256, 256>>>(b1, p_x2);
    scatter_agg_kernel<<<NN, 256>>>(p_x2);

    // --- GAT layer 2 ---
    prep_A_kernel<<<pa_grid, 256>>>(p_x2, NN);
    prep_B_kernel<<<pb_grid, 256>>>(W2);
    frag_gemm_kernel<<<ggrid, 256, gemm_smem>>>(p_h, NN);
    ws_kernel<<<CC, 384>>>(W2, a_src2, a_dst2);
    nodescore_kernel<<<NN / 8, 256, ns_smem>>>(p_x2);
    softmax_kernel<<<(NN * 32 + 255) / 256, 256>>>();
    init_out_kernel<<<(NN * CC / 4 + 255) / 256, 256>>>(b2, p_y);
    scatter_agg_kernel<<<NN, 256>>>(p_y);

    // --- pooling + MLP ---
    pool_sum_kernel<<<dim3(GGR, CC / 128), 128>>>(p_y);
    mlp_kernel<<<GGR, 128>>>(mlp_w1, mlp_b1, mlp_w2, mlp_b2, out);
}

// round 7
// speedup vs baseline: 1.8007x; 1.0863x over previous
#include <cuda_runtime.h>
#include <cuda_fp16.h>
#include <cstdint>

// Problem constants
#define NN   10000          // nodes
#define EE   20000          // edges (without self loops)
#define ETOT 30000          // edges + self loops
#define HH   12             // heads
#define CC   768            // per-head dim (== input feature dim)
#define HC   9216           // H*C
#define GGR  64             // graphs

#define MTILES 79           // ceil(10000/128)
#define NTILES 72           // 9216/128
#define KB16   48           // 768/16 k-blocks
#define FRAG_TILE_BYTES 196608

// ---------------- device scratch (static globals; no runtime alloc) --------
__device__ __half g_h16[(size_t)NN * HC];  // per-layer node features, fp16
__device__ float g_x2[NN * CC];            // layer-1 output / layer-2 input
__device__ float g_y[NN * CC];             // layer-2 output
__device__ uint4 g_Afrag[(size_t)MTILES * FRAG_TILE_BYTES / 16];
__device__ uint4 g_Bfrag[(size_t)NTILES * FRAG_TILE_BYTES / 16];
__device__ float g_Wsd[24 * CC];           // fused score weights [24][768]
__device__ float g_s[NN * HH];             // alpha_src per node/head
__device__ float g_d[NN * HH];             // alpha_dst per node/head
__device__ float g_alpha[ETOT * HH];       // softmax weights (pre-scaled by 1/H)
__device__ int   g_indeg[NN];
__device__ int   g_outdeg[NN];
__device__ int   g_rowptr[NN + 1];         // dst CSR
__device__ int   g_srowptr[NN + 1];        // src CSR
__device__ int   g_fill[NN];
__device__ int   g_sfill[NN];
__device__ int   g_ssrc[ETOT];             // src node per dst-CSR position
__device__ int   g_sdst[ETOT];             // dst node per src-CSR position
__device__ int   g_sapos[ETOT];            // alpha (dst-CSR) position per src-CSR pos
__device__ float g_pool[GGR * CC];
__device__ int   g_cnt[GGR];
__device__ int   g_gstart[GGR];

// ---------------- helpers ----------------------------------------------------
__device__ __forceinline__ uint32_t smem_u32(const void* p) {
    uint32_t a;
    asm("{ .reg .u64 t; cvta.to.shared.u64 t, %1; cvt.u32.u64 %0, t; }"
        : "=r"(a) : "l"(p));
    return a;
}

__device__ __forceinline__ unsigned pack2(float lo, float hi) {
    __half2 h = __floats2half2_rn(lo, hi);
    return *reinterpret_cast<unsigned*>(&h);
}

__device__ __forceinline__ void mma_fp16(float* d, const unsigned* a,
                                         unsigned b0, unsigned b1) {
    asm volatile(
        "mma.sync.aligned.m16n8k16.row.col.f32.f16.f16.f32 "
        "{%0,%1,%2,%3}, {%4,%5,%6,%7}, {%8,%9}, {%0,%1,%2,%3};\n"
        : "+f"(d[0]), "+f"(d[1]), "+f"(d[2]), "+f"(d[3])
        : "r"(a[0]), "r"(a[1]), "r"(a[2]), "r"(a[3]), "r"(b0), "r"(b1));
}

#define CP_ASYNC16(dst, src) \
    asm volatile("cp.async.cg.shared.global [%0], [%1], 16;" :: \
                 "r"(dst), "l"(src) : "memory")
#define CP_COMMIT() asm volatile("cp.async.commit_group;" ::: "memory")
#define CP_WAIT1()  asm volatile("cp.async.wait_group 1;" ::: "memory")
#define CP_WAIT0()  asm volatile("cp.async.wait_group 0;" ::: "memory")

#define LDS128(r0, r1, r2, r3, addr) \
    asm volatile("ld.shared.v4.b32 {%0,%1,%2,%3}, [%4];" \
                 : "=r"(r0), "=r"(r1), "=r"(r2), "=r"(r3) : "r"(addr))

// ---------------- CSR build ------------------------------------------------
__global__ void zero_build_kernel() {
    int i = blockIdx.x * blockDim.x + threadIdx.x;
    if (i < NN) { g_indeg[i] = 0; g_fill[i] = 0; g_outdeg[i] = 0; g_sfill[i] = 0; }
    if (i < GGR) { g_cnt[i] = 0; g_gstart[i] = NN; }
}

__global__ void count_deg_kernel(const int* __restrict__ edge_index) {
    int e = blockIdx.x * blockDim.x + threadIdx.x;
    if (e >= ETOT) return;
    int src = (e < EE) ? edge_index[e]      : (e - EE);
    int dst = (e < EE) ? edge_index[EE + e] : (e - EE);
    atomicAdd(&g_indeg[dst], 1);
    atomicAdd(&g_outdeg[src], 1);
}

// fast exclusive scan: 10 elems/thread + shuffle scan (1024 threads)
__device__ void scan_one(const int* __restrict__ deg, int* __restrict__ rowptr) {
    __shared__ int wsum[32];
    int t = threadIdx.x, lane = t & 31, wid = t >> 5;
    int base = t * 10;
    int loc[10];
    int s = 0;
#pragma unroll
    for (int i = 0; i < 10; i++) {
        int idx = base + i;
        int v = (idx < NN) ? deg[idx] : 0;
        loc[i] = s;
        s += v;
    }
    int incl = s;
#pragma unroll
    for (int o = 1; o < 32; o <<= 1) {
        int x = __shfl_up_sync(0xffffffffu, incl, o);
        if (lane >= o) incl += x;
    }
    if (lane == 31) wsum[wid] = incl;
    __syncthreads();
    if (wid == 0) {
        int w = wsum[lane];
#pragma unroll
        for (int o = 1; o < 32; o <<= 1) {
            int x = __shfl_up_sync(0xffffffffu, w, o);
            if (lane >= o) w += x;
        }
        wsum[lane] = w;
    }
    __syncthreads();
    int off = incl - s + (wid ? wsum[wid - 1] : 0);
#pragma unroll
    for (int i = 0; i < 10; i++) {
        int idx = base + i;
        if (idx <= NN) rowptr[idx] = off + loc[i];
    }
    __syncthreads();
}

__global__ void scan2_kernel() {
    scan_one(g_indeg,  g_rowptr);
    scan_one(g_outdeg, g_srowptr);
}

__global__ void fill_both_kernel(const int* __restrict__ edge_index) {
    int e = blockIdx.x * blockDim.x + threadIdx.x;
    if (e >= ETOT) return;
    int src = (e < EE) ? edge_index[e]      : (e - EE);
    int dst = (e < EE) ? edge_index[EE + e] : (e - EE);
    int pd = g_rowptr[dst] + atomicAdd(&g_fill[dst], 1);
    g_ssrc[pd] = src;
    int ps = g_srowptr[src] + atomicAdd(&g_sfill[src], 1);
    g_sdst[ps]  = dst;
    g_sapos[ps] = pd;
}

__global__ void graph_start_kernel(const int* __restrict__ batch) {
    int n = blockIdx.x * blockDim.x + threadIdx.x;
    if (n < NN) {
        atomicMin(&g_gstart[batch[n]], n);
        atomicAdd(&g_cnt[batch[n]], 1);
    }
}

// ---------------- fp16 fragment packing --------------------------------------
__global__ __launch_bounds__(256)
void prep_A_kernel(const float* __restrict__ src, int M) {
    __shared__ float st[128 * 68];       // 128 rows x 64 k, pitch 68
    int tid = threadIdx.x, lane = tid & 31, wid = tid >> 5;
    int mtile = blockIdx.x, kgrp = blockIdx.y;
#pragma unroll
    for (int i = 0; i < 8; i++) {
        int idx = tid + i * 256;
        int row = idx >> 4, c4 = idx & 15;
        int m = mtile * 128 + row;
        float4 v = make_float4(0.f, 0.f, 0.f, 0.f);
        if (m < M) v = *(const float4*)&src[(size_t)m * CC + kgrp * 64 + c4 * 4];
        *(float4*)&st[row * 68 + c4 * 4] = v;
    }
    __syncthreads();
    int g = lane >> 2, tg = lane & 3;
#pragma unroll
    for (int t = 0; t < 4; t++) {
        int fb  = wid * 4 + t;
        int kbl = fb & 3, m16 = fb >> 2;
        int r0 = m16 * 16 + g, r1 = r0 + 8;
        int k0 = kbl * 16 + 2 * tg;
        uint4 o;
        o.x = pack2(st[r0 * 68 + k0],     st[r0 * 68 + k0 + 1]);
        o.y = pack2(st[r1 * 68 + k0],     st[r1 * 68 + k0 + 1]);
        o.z = pack2(st[r0 * 68 + k0 + 8], st[r0 * 68 + k0 + 9]);
        o.w = pack2(st[r1 * 68 + k0 + 8], st[r1 * 68 + k0 + 9]);
        g_Afrag[(size_t)(mtile * KB16 + kgrp * 4 + kbl) * 256 + m16 * 32 + lane] = o;
    }
}

__global__ __launch_bounds__(256)
void prep_B_kernel(const float* __restrict__ W) {
    __shared__ float st[64 * 132];
    int tid = threadIdx.x, lane = tid & 31, wid = tid >> 5;
    int ntile = blockIdx.x, kgrp = blockIdx.y;
#pragma unroll
    for (int i = 0; i < 8; i++) {
        int idx = tid + i * 256;
        int row = idx >> 5, c4 = idx & 31;
        float4 v = *(const float4*)&W[(size_t)(kgrp * 64 + row) * HC +
                                      ntile * 128 + c4 * 4];
        *(float4*)&st[row * 132 + c4 * 4] = v;
    }
    __syncthreads();
    int g = lane >> 2, tg = lane & 3;
#pragma unroll
    for (int t = 0; t < 4; t++) {
        int fb  = wid * 4 + t;
        int kbl = fb & 3, n16 = fb >> 2;
        int k0 = kbl * 16 + 2 * tg;
        int ne = n16 * 16 + g, no = ne + 8;
        uint4 o;
        o.x = pack2(st[k0 * 132 + ne],       st[(k0 + 1) * 132 + ne]);
        o.y = pack2(st[(k0 + 8) * 132 + ne], st[(k0 + 9) * 132 + ne]);
        o.z = pack2(st[k0 * 132 + no],       st[(k0 + 1) * 132 + no]);
        o.w = pack2(st[(k0 + 8) * 132 + no], st[(k0 + 9) * 132 + no]);
        g_Bfrag[(size_t)(ntile * KB16 + kgrp * 4 + kbl) * 256 + n16 * 32 + lane] = o;
    }
}

// ---------------- fp16 fragment GEMM (fp16 output) ---------------------------
#define NCHK 12
#define STAGE_BYTES 32768

__global__ __launch_bounds__(256)
void frag_gemm_kernel(__half* __restrict__ Hm, int M) {
    extern __shared__ char smem[];
    const uint32_t sbase = smem_u32(smem);
    const int tid = threadIdx.x, wid = tid >> 5, lane = tid & 31;
    const int mtile = blockIdx.y, ntile = blockIdx.x;
    const char* Abase = (const char*)g_Afrag + (size_t)mtile * FRAG_TILE_BYTES;
    const char* Bbase = (const char*)g_Bfrag + (size_t)ntile * FRAG_TILE_BYTES;

    const int g = lane >> 2, tg = lane & 3;
    const int mb16 = (wid & 3) * 2;
    const int nb16 = (wid >> 2) * 4;

    float acc[2][8][4];
#pragma unroll
    for (int i = 0; i < 2; i++)
#pragma unroll
        for (int j = 0; j < 8; j++)
#pragma unroll
            for (int q = 0; q < 4; q++) acc[i][j][q] = 0.f;

#define STAGE_CP(buf, chunk)                                              \
    {                                                                     \
        const char* as = Abase + (size_t)(chunk) * 16384 + tid * 16;      \
        const char* bs = Bbase + (size_t)(chunk) * 16384 + tid * 16;      \
        uint32_t ad = sbase + (buf) * STAGE_BYTES + tid * 16;             \
        uint32_t bd = ad + 16384;                                         \
        _Pragma("unroll")                                                 \
        for (int i = 0; i < 4; i++) {                                     \
            CP_ASYNC16(ad + i * 4096, as + (size_t)i * 4096);             \
            CP_ASYNC16(bd + i * 4096, bs + (size_t)i * 4096);             \
        }                                                                 \
        CP_COMMIT();                                                      \
    }

    STAGE_CP(0, 0)
    STAGE_CP(1, 1)

    for (int it = 0; it < NCHK; it++) {
        if (it + 2 < NCHK) { CP_WAIT1(); } else { CP_WAIT0(); }
        __syncthreads();
        uint32_t sa = sbase + (it & 1) * STAGE_BYTES;
        uint32_t sb = sa + 16384;
#pragma unroll
        for (int kbl = 0; kbl < 4; kbl++) {
            unsigned af[2][4], bf[4][4];
#pragma unroll
            for (int mi = 0; mi < 2; mi++) {
                uint32_t a = sa + (uint32_t)(((kbl * 8 + mb16 + mi) * 32 + lane) * 16);
                LDS128(af[mi][0], af[mi][1], af[mi][2], af[mi][3], a);
            }
#pragma unroll
            for (int j = 0; j < 4; j++) {
                uint32_t a = sb + (uint32_t)(((kbl * 8 + nb16 + j) * 32 + lane) * 16);
                LDS128(bf[j][0], bf[j][1], bf[j][2], bf[j][3], a);
            }
#pragma unroll
            for (int mi = 0; mi < 2; mi++)
#pragma unroll
                for (int j = 0; j < 4; j++) {
                    mma_fp16(acc[mi][2 * j],     af[mi], bf[j][0], bf[j][1]);
                    mma_fp16(acc[mi][2 * j + 1], af[mi], bf[j][2], bf[j][3]);
                }
        }
        __syncthreads();
        if (it + 2 < NCHK) STAGE_CP(it & 1, it + 2)
    }

    const int brow = mtile * 128, bcol = ntile * 128;
    const int wm = (wid & 3) * 32, wn = (wid >> 2) * 64;
#pragma unroll
    for (int mi = 0; mi < 2; mi++) {
#pragma unroll
        for (int nj = 0; nj < 8; nj++) {
            int r = brow + wm + mi * 16 + g;
            int c = bcol + wn + nj * 8 + 2 * tg;
            if (r < M)
                *(__half2*)&Hm[(size_t)r * HC + c] =
                    __floats2half2_rn(acc[mi][nj][0], acc[mi][nj][1]);
            if (r + 8 < M)
                *(__half2*)&Hm[(size_t)(r + 8) * HC + c] =
                    __floats2half2_rn(acc[mi][nj][2], acc[mi][nj][3]);
        }
    }
#undef STAGE_CP
}

// ---------------- fused score weights: Wsd[j][k] ------------------------------
__global__ __launch_bounds__(384)
void ws_kernel(const float* __restrict__ W, const float* __restrict__ a_src,
               const float* __restrict__ a_dst) {
    int k = blockIdx.x;
    int h = threadIdx.x >> 5;
    int lane = threadIdx.x & 31;
    const float* wr = &W[(size_t)k * HC + h * CC];
    const float* as = &a_src[h * CC];
    const float* ad = &a_dst[h * CC];
    float ps = 0.f, pd = 0.f;
#pragma unroll
    for (int i = 0; i < CC / 32; i++) {
        float v = wr[i * 32 + lane];
        ps += v * as[i * 32 + lane];
        pd += v * ad[i * 32 + lane];
    }
    for (int o = 16; o; o >>= 1) {
        ps += __shfl_xor_sync(0xffffffffu, ps, o);
        pd += __shfl_xor_sync(0xffffffffu, pd, o);
    }
    if (lane == 0) {
        g_Wsd[h * CC + k]        = ps;
        g_Wsd[(12 + h) * CC + k] = pd;
    }
}

// ---------------- node scores ------------------------------------------------
__global__ __launch_bounds__(256)
void nodescore_kernel(const float* __restrict__ A) {
    extern __shared__ float sw[];        // [24][768]
    int tid = threadIdx.x, wid = tid >> 5, lane = tid & 31;
#pragma unroll
    for (int i = 0; i < 18; i++) {
        int idx = tid * 4 + i * 1024;
        *(float4*)&sw[idx] = *(const float4*)&g_Wsd[idx];
    }
    __syncthreads();
    int n = blockIdx.x * 8 + wid;
    const float* Ar = &A[(size_t)n * CC];
    float ps[HH], pd[HH];
#pragma unroll
    for (int h = 0; h < HH; h++) { ps[h] = 0.f; pd[h] = 0.f; }
#pragma unroll 4
    for (int i = 0; i < CC / 32; i++) {
        int k = i * 32 + lane;
        float av = Ar[k];
#pragma unroll
        for (int h = 0; h < HH; h++) {
            ps[h] += av * sw[h * CC + k];
            pd[h] += av * sw[(12 + h) * CC + k];
        }
    }
#pragma unroll
    for (int h = 0; h < HH; h++) {
        for (int o = 16; o; o >>= 1) {
            ps[h] += __shfl_xor_sync(0xffffffffu, ps[h], o);
            pd[h] += __shfl_xor_sync(0xffffffffu, pd[h], o);
        }
    }
    if (lane == 0) {
#pragma unroll
        for (int h = 0; h < HH; h++) {
            g_s[n * HH + h] = ps[h];
            g_d[n * HH + h] = pd[h];
        }
    }
}

// ---------------- segment softmax (one THREAD per node/head) ----------------
__global__ void softmax_kernel() {
    int idx = blockIdx.x * blockDim.x + threadIdx.x;
    if (idx >= NN * HH) return;
    int n = idx / HH, h = idx - n * HH;
    float dn = g_d[idx];
    int r0 = g_rowptr[n], r1 = g_rowptr[n + 1];
    float mx = -1e30f;
    for (int p = r0; p < r1; p++) {
        float v = g_s[g_ssrc[p] * HH + h] + dn;
        v = (v > 0.f) ? v : 0.2f * v;
        mx = fmaxf(mx, v);
    }
    float sum = 0.f;
    for (int p = r0; p < r1; p++) {
        float v = g_s[g_ssrc[p] * HH + h] + dn;
        v = (v > 0.f) ? v : 0.2f * v;
        float ex = __expf(v - mx);
        g_alpha[p * HH + h] = ex;
        sum += ex;
    }
    float inv = 1.f / ((float)HH * (sum + 1e-16f));
    for (int p = r0; p < r1; p++) g_alpha[p * HH + h] *= inv;
}

// ---------------- scatter aggregation ----------------------------------------
__global__ void init_out_kernel(const float* __restrict__ bias,
                                float* __restrict__ out) {
    int i = blockIdx.x * blockDim.x + threadIdx.x;
    if (i >= NN * CC / 4) return;
    int c4 = i % (CC / 4);
    ((float4*)out)[i] = ((const float4*)bias)[c4];
}

__global__ __launch_bounds__(256)
void scatter_agg_kernel(float* __restrict__ out) {
    __shared__ float row[HC];            // 36 KB fp32 (converted once)
    int n   = blockIdx.x;
    int tid = threadIdx.x;
    const __half2* hp = (const __half2*)&g_h16[(size_t)n * HC];
#pragma unroll
    for (int i = 0; i < 18; i++) {
        int idx = tid + i * 256;         // half2 index 0..4607
        float2 f = __half22float2(hp[idx]);
        *(float2*)&row[idx * 2] = f;
    }
    int r0 = g_srowptr[n], r1 = g_srowptr[n + 1];
    __syncthreads();
    for (int p = r0; p < r1; p++) {
        int dst  = g_sdst[p];
        int apos = g_sapos[p];
        const float4* ap = (const float4*)&g_alpha[apos * HH];
        float4 a0 = __ldg(&ap[0]);
        float4 a1 = __ldg(&ap[1]);
        float4 a2 = __ldg(&ap[2]);
        float al[HH] = {a0.x, a0.y, a0.z, a0.w, a1.x, a1.y, a1.z, a1.w,
                        a2.x, a2.y, a2.z, a2.w};
        float* op = &out[(size_t)dst * CC];
#pragma unroll
        for (int r = 0; r < 3; r++) {
            int c = tid + r * 256;
            float v = 0.f;
#pragma unroll
            for (int h = 0; h < HH; h++) v += al[h] * row[h * CC + c];
            atomicAdd(&op[c], v);
        }
    }
}

// ---------------- pooling: contiguous segment sum (batch sorted) -------------
__global__ __launch_bounds__(128)
void pool_sum_kernel(const float* __restrict__ xin) {
    int gid = blockIdx.x;
    int col = blockIdx.y * 128 + threadIdx.x;
    int start = g_gstart[gid], cnt = g_cnt[gid];
    float s = 0.f;
    for (int i = 0; i < cnt; i++)
        s += xin[(size_t)(start + i) * CC + col];
    g_pool[gid * CC + col] = s;
}

// ---------------- final MLP (block per graph) -------------------------------
__global__ __launch_bounds__(128)
void mlp_kernel(const float* __restrict__ w1, const float* __restrict__ b1,
                const float* __restrict__ w2, const float* __restrict__ b2,
                float* __restrict__ out) {
    int gid = blockIdx.x;
    int tid = threadIdx.x;
    __shared__ float gv[CC];
    __shared__ float z[128];
    float invc = 1.0f / fmaxf((float)g_cnt[gid], 1.0f);
    for (int c = tid; c < CC; c += 128) gv[c] = g_pool[gid * CC + c] * invc;
    __syncthreads();
    float acc = b1[tid];
    for (int k = 0; k < CC; k++) acc += gv[k] * w1[k * 128 + tid];
    z[tid] = fmaxf(acc, 0.f);
    __syncthreads();
    if (tid < 4) {
        float o = b2[tid];
        for (int j = 0; j < 128; j++) o += z[j] * w2[j * 4 + tid];
        out[gid * 4 + tid] = o;
    }
}

// ---------------- launcher ---------------------------------------------------
extern "C" void kernel_launch(void* const* d_in, const int* in_sizes, int n_in,
                              void* d_out, int out_size) {
    const float* x        = (const float*)d_in[0];
    const int*   eidx     = (const int*)  d_in[1];
    const int*   batch    = (const int*)  d_in[2];
    const float* W1       = (const float*)d_in[3];
    const float* a_src1   = (const float*)d_in[4];
    const float* a_dst1   = (const float*)d_in[5];
    const float* b1       = (const float*)d_in[6];
    const float* W2       = (const float*)d_in[7];
    const float* a_src2   = (const float*)d_in[8];
    const float* a_dst2   = (const float*)d_in[9];
    const float* b2       = (const float*)d_in[10];
    const float* mlp_w1   = (const float*)d_in[11];
    const float* mlp_b1   = (const float*)d_in[12];
    const float* mlp_w2   = (const float*)d_in[13];
    const float* mlp_b2   = (const float*)d_in[14];
    float* out = (float*)d_out;

    __half* p_h;
    float *p_x2, *p_y;
    cudaGetSymbolAddress((void**)&p_h,  g_h16);
    cudaGetSymbolAddress((void**)&p_x2, g_x2);
    cudaGetSymbolAddress((void**)&p_y,  g_y);

    const int gemm_smem = 2 * STAGE_BYTES;     // 65536
    cudaFuncSetAttribute(frag_gemm_kernel,
                         cudaFuncAttributeMaxDynamicSharedMemorySize, gemm_smem);
    const int ns_smem = 24 * CC * 4;           // 73728
    cudaFuncSetAttribute(nodescore_kernel,
                         cudaFuncAttributeMaxDynamicSharedMemorySize, ns_smem);

    // --- CSR build (dst + src) + graph segments ---
    zero_build_kernel<<<(NN + 255) / 256, 256>>>();
    count_deg_kernel<<<(ETOT + 255) / 256, 256>>>(eidx);
    scan2_kernel<<<1, 1024>>>();
    fill_both_kernel<<<(ETOT + 255) / 256, 256>>>(eidx);
    graph_start_kernel<<<(NN + 255) / 256, 256>>>(batch);

    dim3 pa_grid(MTILES, 12);
    dim3 pb_grid(NTILES, 12);
    dim3 ggrid(NTILES, MTILES);

    // --- GAT layer 1 ---
    prep_A_kernel<<<pa_grid, 256>>>(x, NN);
    prep_B_kernel<<<pb_grid, 256>>>(W1);
    frag_gemm_kernel<<<ggrid, 256, gemm_smem>>>(p_h, NN);
    ws_kernel<<<CC, 384>>>(W1, a_src1, a_dst1);
    nodescore_kernel<<<NN / 8, 256, ns_smem>>>(x);
    softmax_kernel<<<(NN * HH + 255) / 256, 256>>>();
    init_out_kernel<<<(NN * CC / 4 + 255) / 256, 256>>>(b1, p_x2);
    scatter_agg_kernel<<<NN, 256>>>(p_x2);

    // --- GAT layer 2 ---
    prep_A_kernel<<<pa_grid, 256>>>(p_x2, NN);
    prep_B_kernel<<<pb_grid, 256>>>(W2);
    frag_gemm_kernel<<<ggrid, 256, gemm_smem>>>(p_h, NN);
    ws_kernel<<<CC, 384>>>(W2, a_src2, a_dst2);
    nodescore_kernel<<<NN / 8, 256, ns_smem>>>(p_x2);
    softmax_kernel<<<(NN * HH + 255) / 256, 256>>>();
    init_out_kernel<<<(NN * CC / 4 + 255) / 256, 256>>>(b2, p_y);
    scatter_agg_kernel<<<NN, 256>>>(p_y);

    // --- pooling + MLP ---
    pool_sum_kernel<<<dim3(GGR, CC / 128), 128>>>(p_y);
    mlp_kernel<<<GGR, 128>>>(mlp_w1, mlp_b1, mlp_w2, mlp_b2, out);
}